// round 8
// baseline (speedup 1.0000x reference)
#include <cuda_runtime.h>
#include <math.h>

#define B 4
#define L 2048
#define H 8
#define D 64
#define S 40
#define U 40
#define HD (H*D)
#define CHUNK 128
#define NCHUNK (L/CHUNK)     /* 16 scan chunks */
#define KCHUNK 256
#define NKC (L/KCHUNK)       /* 8 key chunks for M pass */
#define ROWF 72              /* padded smem row: 64 data + 8 pad floats */
#define SCALE 0.125f         /* 1/sqrt(64) */

// scratch (allocation-free rule: __device__ globals)
__device__ float2   g_pM[B*H*NKC*L];      // per-(bh,kc,q) partial {max,sum}
__device__ int      g_top[B*H*U];
__device__ float    g_agg[B*H*NCHUNK*D];  // scan chunk aggregates
__device__ int      g_flag[B*H*NCHUNK];   // lookback flags
__device__ unsigned g_ent[NKC*L*S];       // binned sample lists (bh-independent)
__device__ unsigned g_cnt[NKC*L];         // list lengths

// ---------------------------------------------------------------------------
// Kernel 0: bin samples by key-chunk (idx is shared across all b,h).
// Thread per q; appends in s-order (deterministic). Also clears scan flags.
// ---------------------------------------------------------------------------
__global__ void bin_kernel(const int* __restrict__ idx) {
    int gid = blockIdx.x*256 + threadIdx.x;      // 8*256 = 2048
    if (gid < B*H*NCHUNK) g_flag[gid] = 0;
    int q = gid;
    unsigned c[NKC];
    #pragma unroll
    for (int i = 0; i < NKC; i++) c[i] = 0;
    #pragma unroll
    for (int s = 0; s < S; s++) {
        int k  = __ldg(idx + q*S + s);
        int kc = k >> 8;                          // KCHUNK = 256
        g_ent[(kc*L + q)*S + c[kc]] = (unsigned)k;
        c[kc]++;
    }
    #pragma unroll
    for (int kc = 0; kc < NKC; kc++) g_cnt[kc*L + q] = c[kc];
}

// ---------------------------------------------------------------------------
// Kernel 1: partial M over one 256-key chunk held in SMEM (key-stationary).
// Block = (bh, kc); 8 warps sweep all 2048 queries. Per query: 4 groups of
// 8 lanes each process one binned entry per round, dotting the smem K row
// (padded stride 72 -> groups land on distinct bank clusters).
// ---------------------------------------------------------------------------
__global__ void compute_M_kernel(const float* __restrict__ Q,
                                 const float* __restrict__ K,
                                 const int*   __restrict__ idxunused) {
    int kc = blockIdx.x & (NKC-1);
    int bh = blockIdx.x >> 3;
    int h  = bh & (H-1), b = bh >> 3;

    extern __shared__ float sK[];                 // [256][ROWF]
    float4* sK4 = (float4*)sK;

    // load K chunk: 256 rows x 16 float4, coalesced
    {
        int t = threadIdx.x;
        const float* kbase = K + (((size_t)b*L + (size_t)kc*KCHUNK)*H + h)*D;
        #pragma unroll
        for (int i = 0; i < 16; i++) {
            int e   = t + 256*i;                  // 0..4095
            int row = e >> 4, c4 = e & 15;
            sK4[row*(ROWF/4) + c4] =
                *(const float4*)(kbase + (size_t)row*HD + c4*4);
        }
    }
    __syncthreads();

    int warp = threadIdx.x >> 5, lane = threadIdx.x & 31;
    int g = lane >> 3, sub = lane & 7;            // 4 groups x 8 lanes

    for (int q = warp; q < L; q += 8) {
        const float4* qrow = (const float4*)(Q + ((size_t)b*L + q)*HD + (size_t)h*D);
        float4 q0 = qrow[sub];
        float4 q1 = qrow[8 + sub];

        unsigned cnt  = g_cnt[kc*L + q];
        const unsigned* ent = g_ent + ((size_t)kc*L + q)*S;

        float mx = -INFINITY, sm = 0.f;
        for (unsigned bj = 0; bj < cnt; bj += 4) {
            unsigned j = bj + g;
            bool valid = (j < cnt);
            unsigned kk = ent[valid ? j : 0];     // broadcast within group
            int kl = (int)(kk & (KCHUNK-1));
            float4 a0 = sK4[kl*(ROWF/4) + sub];
            float4 a1 = sK4[kl*(ROWF/4) + 8 + sub];
            float p = q0.x*a0.x + q0.y*a0.y + q0.z*a0.z + q0.w*a0.w
                    + q1.x*a1.x + q1.y*a1.y + q1.z*a1.z + q1.w*a1.w;
            p += __shfl_xor_sync(0xffffffffu, p, 1);
            p += __shfl_xor_sync(0xffffffffu, p, 2);
            p += __shfl_xor_sync(0xffffffffu, p, 4);
            if (valid) { mx = fmaxf(mx, p); sm += p; }
        }
        // reduce across the 4 groups
        mx = fmaxf(mx, __shfl_xor_sync(0xffffffffu, mx, 8));
        sm += __shfl_xor_sync(0xffffffffu, sm, 8);
        mx = fmaxf(mx, __shfl_xor_sync(0xffffffffu, mx, 16));
        sm += __shfl_xor_sync(0xffffffffu, sm, 16);

        if (lane == 0) g_pM[((size_t)bh*NKC + kc)*L + q] = make_float2(mx, sm);
    }
}

// ---------------------------------------------------------------------------
// Kernel 2: combine chunk partials -> M, then top-40 per (b,h).
// One warp per (b,h); register-resident order-preserving uint32 values,
// packed (val, ~idx) u64 butterfly max; loser lane rescans its 64 slots.
// ---------------------------------------------------------------------------
__device__ __forceinline__ unsigned order_f32(float v) {
    unsigned u = __float_as_uint(v);
    return (u & 0x80000000u) ? ~u : (u | 0x80000000u);
}

__global__ void topk_kernel() {
    int bh   = blockIdx.x;
    int lane = threadIdx.x;           // block = 32
    const float2* P = g_pM + (size_t)bh*NKC*L;

    unsigned ov[64];
    #pragma unroll
    for (int j = 0; j < 64; j++) {
        int q = j*32 + lane;
        float mx = -INFINITY, sm = 0.f;
        #pragma unroll
        for (int kc = 0; kc < NKC; kc++) {
            float2 c = P[kc*L + q];
            mx = fmaxf(mx, c.x);
            sm += c.y;
        }
        ov[j] = order_f32(mx - sm * (1.0f/(float)L));
    }

    unsigned long long removed = 0ull;
    unsigned bv = 0; int bslot = 0;
    #pragma unroll
    for (int j = 0; j < 64; j++) if (ov[j] > bv) { bv = ov[j]; bslot = j; }

    for (int u = 0; u < U; u++) {
        unsigned long long key =
            ((unsigned long long)bv << 32) | (unsigned)(~(unsigned)(bslot*32 + lane));
        #pragma unroll
        for (int o = 16; o > 0; o >>= 1) {
            unsigned long long ok = __shfl_xor_sync(0xffffffffu, key, o);
            if (ok > key) key = ok;
        }
        int widx = (int)(~(unsigned)key);
        if (lane == 0) g_top[bh*U + u] = widx;
        if ((widx & 31) == lane) {
            removed |= 1ull << (widx >> 5);
            bv = 0; bslot = 0;
            #pragma unroll
            for (int j = 0; j < 64; j++) {
                unsigned v = ((removed >> j) & 1ull) ? 0u : ov[j];
                if (v > bv) { bv = v; bslot = j; }
            }
        }
    }
}

// ---------------------------------------------------------------------------
// Kernel 3: fused cumsum(V) over L via decoupled lookback. One kernel, one V
// read, one out write. Block = (bh, c); all 512 blocks resident in one wave.
// ---------------------------------------------------------------------------
__global__ void scan_kernel(const float* __restrict__ V, float* __restrict__ out) {
    int blk = blockIdx.x;
    int c   = blk % NCHUNK;
    int bh  = blk / NCHUNK;
    int h   = bh & (H-1), b = bh >> 3;
    int t   = threadIdx.x;            // 256
    __shared__ float tile[CHUNK*D];   // 32KB
    __shared__ float part[4][64];
    __shared__ float offs[4][64];

    size_t base = (((size_t)b*L + (size_t)c*CHUNK))*HD + (size_t)h*D;
    for (int e = t; e < CHUNK*D/4; e += 256) {
        int q = e >> 4, d4 = e & 15;
        ((float4*)tile)[q*16 + d4] = *(const float4*)(V + base + (size_t)q*HD + d4*4);
    }
    __syncthreads();

    // intra-part serial scan: 4 parts x 64 d-lanes, 32 rows each
    int p = t >> 6, d = t & 63;
    {
        float acc = 0.f;
        #pragma unroll
        for (int i = 0; i < 32; i++) {
            acc += tile[(p*32 + i)*64 + d];
            tile[(p*32 + i)*64 + d] = acc;
        }
        part[p][d] = acc;
    }
    __syncthreads();

    // publish chunk aggregate (release)
    if (t < 64) g_agg[blk*D + t] = part[0][t] + part[1][t] + part[2][t] + part[3][t];
    __syncthreads();
    if (t == 0) { __threadfence(); atomicExch(&g_flag[blk], 1); }

    // lookback: wait for all predecessors, then sum their aggregates
    if (t < c) while (atomicAdd(&g_flag[bh*NCHUNK + t], 0) == 0) {}
    __syncthreads();
    __threadfence();
    if (t < 64) {
        float o = 0.f;
        for (int cc = 0; cc < c; cc++) o += g_agg[(bh*NCHUNK + cc)*D + t];
        offs[0][t] = o;          o += part[0][t];
        offs[1][t] = o;          o += part[1][t];
        offs[2][t] = o;          o += part[2][t];
        offs[3][t] = o;
    }
    __syncthreads();

    for (int e = t; e < CHUNK*D/4; e += 256) {
        int q = e >> 4, d4 = e & 15;
        float4 v  = ((float4*)tile)[q*16 + d4];
        float4 of = *(float4*)&offs[q >> 5][d4*4];
        v.x += of.x; v.y += of.y; v.z += of.z; v.w += of.w;
        *(float4*)(out + base + (size_t)q*HD + d4*4) = v;
    }
}

// ---------------------------------------------------------------------------
// Kernel 4: attention for the 40 selected queries per (b,h); scatter into out.
// Rank-i row attends only keys 0..i (Informer mask quirk: mask is triu(u,L)).
// Grid = (bh, group of 8 rows) = 160 blocks; one warp per output row.
// Loads only the K/V rows its group can reference (0..8g+7).
// ---------------------------------------------------------------------------
__global__ void attn_kernel(const float* __restrict__ Q,
                            const float* __restrict__ K,
                            const float* __restrict__ V,
                            float* __restrict__ out) {
    int g  = blockIdx.x % 5;
    int bh = blockIdx.x / 5;
    int h  = bh & (H-1), b = bh >> 3;
    int t  = threadIdx.x;     // 256 = 8 warps
    __shared__ float Ks[U][D+1], Vs[U][D+1], Qs[8][D+1];
    __shared__ int ti[8];

    if (t < 8) ti[t] = g_top[bh*U + g*8 + t];
    __syncthreads();

    int kmax = g*8 + 8;                           // rows 0..kmax-1 needed
    for (int e = t; e < kmax*D; e += 256) {
        int r = e >> 6, d = e & 63;
        Ks[r][d] = K[(((size_t)b*L + r)*H + h)*D + d];
        Vs[r][d] = V[(((size_t)b*L + r)*H + h)*D + d];
    }
    for (int e = t; e < 8*D; e += 256) {
        int r = e >> 6, d = e & 63;
        Qs[r][d] = Q[(((size_t)b*L + ti[r])*H + h)*D + d];
    }
    __syncthreads();

    int warp = t >> 5, lane = t & 31;
    int i  = g*8 + warp;                          // output row rank 0..39
    int k2l = lane + 32;
    int k2 = (k2l < kmax) ? k2l : lane;           // clamp to loaded rows

    bool v0 = (lane <= i);
    bool v1 = (k2l < U) && (k2l <= i);

    float s0 = 0.f, s1 = 0.f;
    #pragma unroll
    for (int d = 0; d < D; d++) {
        float qd = Qs[warp][d];
        s0 += qd * Ks[lane][d];
        s1 += qd * Ks[k2][d];
    }
    s0 *= SCALE; s1 *= SCALE;

    float mx = fmaxf(v0 ? s0 : -INFINITY, v1 ? s1 : -INFINITY);
    #pragma unroll
    for (int o = 16; o > 0; o >>= 1)
        mx = fmaxf(mx, __shfl_xor_sync(0xffffffffu, mx, o));

    float e0 = v0 ? __expf(s0 - mx) : 0.f;
    float e1 = v1 ? __expf(s1 - mx) : 0.f;
    float den = e0 + e1;
    #pragma unroll
    for (int o = 16; o > 0; o >>= 1)
        den += __shfl_xor_sync(0xffffffffu, den, o);
    float inv = __frcp_rn(den);
    float w0 = e0 * inv, w1 = e1 * inv;

    float a0 = 0.f, a1 = 0.f;
    int klim = (i < 31) ? i : 31;
    for (int k = 0; k <= klim; k++) {
        float w = __shfl_sync(0xffffffffu, w0, k);
        a0 += w * Vs[k][lane];
        a1 += w * Vs[k][lane+32];
    }
    for (int k = 32; k <= i; k++) {               // only when i >= 32
        float w = __shfl_sync(0xffffffffu, w1, k - 32);
        a0 += w * Vs[k][lane];
        a1 += w * Vs[k][lane+32];
    }

    float* op = out + (((size_t)b*L + ti[warp])*H + h)*D;
    op[lane]      = a0;
    op[lane + 32] = a1;
}

// ---------------------------------------------------------------------------
extern "C" void kernel_launch(void* const* d_in, const int* in_sizes, int n_in,
                              void* d_out, int out_size) {
    const float* Q   = (const float*)d_in[0];
    const float* K   = (const float*)d_in[1];
    const float* V   = (const float*)d_in[2];
    const int*   idx = (const int*)d_in[3];
    float* out = (float*)d_out;

    const int SK_BYTES = KCHUNK*ROWF*4;   // 73728
    cudaFuncSetAttribute(compute_M_kernel,
                         cudaFuncAttributeMaxDynamicSharedMemorySize, SK_BYTES);

    // 0: bin samples by key-chunk (also clears scan flags)
    bin_kernel<<<8, 256>>>(idx);
    // 1: partial M per (bh, key-chunk), key-stationary in smem
    compute_M_kernel<<<B*H*NKC, 256, SK_BYTES>>>(Q, K, idx);
    // 2: combine partials + top-40 per (b,h)
    topk_kernel<<<B*H, 32>>>();
    // 3: fused single-pass cumsum of V (decoupled lookback)
    scan_kernel<<<B*H*NCHUNK, 256>>>(V, out);
    // 4: sparse attention + scatter (after cumsum writes)
    attn_kernel<<<B*H*5, 256>>>(Q, K, V, out);
}

// round 11
// speedup vs baseline: 3.1350x; 3.1350x over previous
#include <cuda_runtime.h>
#include <math.h>

#define B 4
#define L 2048
#define H 8
#define D 64
#define S 40
#define U 40
#define HD (H*D)
#define CHUNK 128
#define NCHUNK (L/CHUNK)     /* 16 scan chunks */
#define SCALE 0.125f         /* 1/sqrt(64) */

// scratch (allocation-free rule: __device__ globals)
__device__ float g_M[B*H*L];
__device__ float g_agg[B*H*NCHUNK*D];    // scan chunk aggregates
__device__ int   g_flag[B*H*NCHUNK];     // lookback flags
__device__ int   g_sel[B*H*L];           // rank+1 if q selected, else 0
__device__ float g_upd[B*H*U*D];         // attention results per rank

// ---------------------------------------------------------------------------
// Kernel 1: M[b,h,q] = max_s dot(Q[b,h,q], K[b,h,idx[q,s]]) - sum_s/L
// One warp per (b,h,q). 4 groups of 8 lanes; each group owns one key per
// batch and reads its 256B row as 2x(8 lanes x 16B) = ONE 128B line per LDG.
// Also clears g_sel and g_flag (runs first in stream).
// ---------------------------------------------------------------------------
__global__ void compute_M_kernel(const float* __restrict__ Q,
                                 const float* __restrict__ K,
                                 const int*   __restrict__ idx) {
    if (blockIdx.x < 256) {
        g_sel[blockIdx.x*256 + threadIdx.x] = 0;
    } else if (blockIdx.x < 258) {
        int f = (blockIdx.x - 256)*256 + threadIdx.x;
        if (f < B*H*NCHUNK) g_flag[f] = 0;
    }

    int gw   = (blockIdx.x * blockDim.x + threadIdx.x) >> 5;
    int lane = threadIdx.x & 31;
    if (gw >= B*H*L) return;
    int q = gw % L;
    int h = (gw / L) % H;
    int b = gw / (L*H);
    int g   = lane >> 3;     // group 0..3: which key in the batch
    int sub = lane & 7;      // 16B slice within the 128B half-row

    const float4* qrow = (const float4*)(Q + ((size_t)b*L + q)*HD + (size_t)h*D);
    float4 q0 = qrow[sub];        // dims [4*sub   .. 4*sub+3]
    float4 q1 = qrow[8 + sub];    // dims [32+4*sub .. ]

    int k0v = __ldg(idx + q*S + lane);
    int k1v = (lane < 8) ? __ldg(idx + q*S + 32 + lane) : 0;

    const size_t bhK = ((size_t)b*L)*HD + (size_t)h*D;

    float mx = -INFINITY, sm = 0.f;
    #pragma unroll
    for (int t = 0; t < 10; t++) {
        int srcl = t*4 + g;
        int kk = (srcl < 32) ? __shfl_sync(0xffffffffu, k0v, srcl)
                             : __shfl_sync(0xffffffffu, k1v, srcl - 32);
        const float4* krow = (const float4*)(K + bhK + (size_t)kk*HD);
        float4 k0 = krow[sub];
        float4 k1 = krow[8 + sub];
        float p = q0.x*k0.x + q0.y*k0.y + q0.z*k0.z + q0.w*k0.w
                + q1.x*k1.x + q1.y*k1.y + q1.z*k1.z + q1.w*k1.w;
        // reduce within the 8-lane group -> full 64-dim dot on every lane
        p += __shfl_xor_sync(0xffffffffu, p, 1);
        p += __shfl_xor_sync(0xffffffffu, p, 2);
        p += __shfl_xor_sync(0xffffffffu, p, 4);
        mx = fmaxf(mx, p);
        sm += p;
    }
    // reduce across the 4 groups
    mx = fmaxf(mx, __shfl_xor_sync(0xffffffffu, mx, 8));
    sm += __shfl_xor_sync(0xffffffffu, sm, 8);
    mx = fmaxf(mx, __shfl_xor_sync(0xffffffffu, mx, 16));
    sm += __shfl_xor_sync(0xffffffffu, sm, 16);

    if (lane == 0) g_M[gw] = mx - sm * (1.0f/(float)L);
}

// ---------------------------------------------------------------------------
// Kernel 2: top-40 per (b,h) + sparse attention into scratch.
// Warp 0 runs the register-resident topk (descending, ties -> smaller index,
// matching lax.top_k) while warps 1-7 stage K/V rows 0..39 into smem.
// Then all 8 warps compute attention (warp per output rank, 5 rounds);
// rank-r row attends only keys 0..r (Informer mask: triu(u,L) on ranks).
// Results -> g_upd, membership map -> g_sel. Nothing touches `out`.
// ---------------------------------------------------------------------------
__device__ __forceinline__ unsigned order_f32(float v) {
    unsigned u = __float_as_uint(v);
    return (u & 0x80000000u) ? ~u : (u | 0x80000000u);
}

__global__ void topk_attn_kernel(const float* __restrict__ Q,
                                 const float* __restrict__ K,
                                 const float* __restrict__ V) {
    int bh = blockIdx.x;
    int h  = bh & (H-1), b = bh >> 3;
    int t  = threadIdx.x;          // 256 = 8 warps
    int warp = t >> 5, lane = t & 31;

    __shared__ float Ks[U][D+1], Vs[U][D+1], Qs[8][D+1];
    __shared__ int ti[U];

    if (warp == 0) {
        // ---- top-40 (proven register form) ----
        const float* M = g_M + bh*L;
        unsigned ov[64];
        #pragma unroll
        for (int j = 0; j < 64; j++) ov[j] = order_f32(M[j*32 + lane]);

        unsigned long long removed = 0ull;
        unsigned bv = 0; int bslot = 0;
        #pragma unroll
        for (int j = 0; j < 64; j++) if (ov[j] > bv) { bv = ov[j]; bslot = j; }

        for (int u = 0; u < U; u++) {
            unsigned long long key =
                ((unsigned long long)bv << 32) | (unsigned)(~(unsigned)(bslot*32 + lane));
            #pragma unroll
            for (int o = 16; o > 0; o >>= 1) {
                unsigned long long ok = __shfl_xor_sync(0xffffffffu, key, o);
                if (ok > key) key = ok;
            }
            int widx = (int)(~(unsigned)key);
            if (lane == 0) { ti[u] = widx; g_sel[bh*L + widx] = u + 1; }
            if ((widx & 31) == lane) {
                removed |= 1ull << (widx >> 5);
                bv = 0; bslot = 0;
                #pragma unroll
                for (int j = 0; j < 64; j++) {
                    unsigned v = ((removed >> j) & 1ull) ? 0u : ov[j];
                    if (v > bv) { bv = v; bslot = j; }
                }
            }
        }
    } else {
        // ---- warps 1-7: stage K/V rows 0..39 (overlaps topk latency) ----
        for (int e = t - 32; e < U*D; e += 224) {
            int r = e >> 6, d = e & 63;
            Ks[r][d] = K[((size_t)b*L + r)*HD + (size_t)h*D + d];
            Vs[r][d] = V[((size_t)b*L + r)*HD + (size_t)h*D + d];
        }
    }
    __syncthreads();

    // ---- attention: warp per rank i, 5 rounds ----
    int k2 = (lane < U-32) ? lane + 32 : lane;   // lanes 0..7 also own keys 32..39

    for (int i = warp; i < U; i += 8) {
        const float* qp = Q + ((size_t)b*L + ti[i])*HD + (size_t)h*D;
        Qs[warp][lane]      = qp[lane];
        Qs[warp][lane + 32] = qp[lane + 32];
        __syncwarp();

        bool v0 = (lane <= i);
        bool v1 = (lane < U-32) && (lane + 32 <= i);

        float s0 = 0.f, s1 = 0.f;
        #pragma unroll
        for (int d = 0; d < D; d++) {
            float qd = Qs[warp][d];
            s0 += qd * Ks[lane][d];
            s1 += qd * Ks[k2][d];
        }
        s0 *= SCALE; s1 *= SCALE;

        float mx = fmaxf(v0 ? s0 : -INFINITY, v1 ? s1 : -INFINITY);
        #pragma unroll
        for (int o = 16; o > 0; o >>= 1)
            mx = fmaxf(mx, __shfl_xor_sync(0xffffffffu, mx, o));

        float e0 = v0 ? __expf(s0 - mx) : 0.f;
        float e1 = v1 ? __expf(s1 - mx) : 0.f;
        float den = e0 + e1;
        #pragma unroll
        for (int o = 16; o > 0; o >>= 1)
            den += __shfl_xor_sync(0xffffffffu, den, o);
        float inv = __frcp_rn(den);
        float w0 = e0 * inv, w1 = e1 * inv;

        float a0 = 0.f, a1 = 0.f;
        int klim = (i < 31) ? i : 31;
        for (int k = 0; k <= klim; k++) {
            float w = __shfl_sync(0xffffffffu, w0, k);
            a0 += w * Vs[k][lane];
            a1 += w * Vs[k][lane+32];
        }
        for (int k = 32; k <= i; k++) {           // only when i >= 32
            float w = __shfl_sync(0xffffffffu, w1, k - 32);
            a0 += w * Vs[k][lane];
            a1 += w * Vs[k][lane+32];
        }

        float* up = g_upd + ((size_t)bh*U + i)*D;
        up[lane]      = a0;
        up[lane + 32] = a1;
        __syncwarp();
    }
}

// ---------------------------------------------------------------------------
// Kernel 3: fused cumsum(V) over L via decoupled lookback; at the final write
// each row checks the selection map and writes the attention result instead.
// Block = (bh, c); all 512 blocks resident in one wave (proven at R7).
// ---------------------------------------------------------------------------
__global__ void scan_kernel(const float* __restrict__ V, float* __restrict__ out) {
    int blk = blockIdx.x;
    int c   = blk & (NCHUNK-1);
    int bh  = blk >> 4;
    int h   = bh & (H-1), b = bh >> 3;
    int t   = threadIdx.x;            // 256
    __shared__ float tile[CHUNK*D];   // 32KB
    __shared__ float part[4][64];
    __shared__ float offs[4][64];
    __shared__ int   sel[CHUNK];

    if (t < CHUNK) sel[t] = g_sel[bh*L + c*CHUNK + t];

    size_t base = (((size_t)b*L + (size_t)c*CHUNK))*HD + (size_t)h*D;
    for (int e = t; e < CHUNK*D/4; e += 256) {
        int q = e >> 4, d4 = e & 15;
        ((float4*)tile)[q*16 + d4] = *(const float4*)(V + base + (size_t)q*HD + d4*4);
    }
    __syncthreads();

    // intra-part serial scan: 4 parts x 64 d-lanes, 32 rows each
    int p = t >> 6, d = t & 63;
    {
        float acc = 0.f;
        #pragma unroll
        for (int i = 0; i < 32; i++) {
            acc += tile[(p*32 + i)*64 + d];
            tile[(p*32 + i)*64 + d] = acc;
        }
        part[p][d] = acc;
    }
    __syncthreads();

    // publish chunk aggregate (release)
    if (t < 64) g_agg[blk*D + t] = part[0][t] + part[1][t] + part[2][t] + part[3][t];
    __syncthreads();
    if (t == 0) { __threadfence(); atomicExch(&g_flag[blk], 1); }

    // lookback: wait for all predecessors, then sum their aggregates
    if (t < c) while (atomicAdd(&g_flag[bh*NCHUNK + t], 0) == 0) {}
    __syncthreads();
    __threadfence();
    if (t < 64) {
        float o = 0.f;
        for (int cc = 0; cc < c; cc++) o += g_agg[(bh*NCHUNK + cc)*D + t];
        offs[0][t] = o;          o += part[0][t];
        offs[1][t] = o;          o += part[1][t];
        offs[2][t] = o;          o += part[2][t];
        offs[3][t] = o;
    }
    __syncthreads();

    for (int e = t; e < CHUNK*D/4; e += 256) {
        int q = e >> 4, d4 = e & 15;
        float4 v;
        int r = sel[q];
        if (r) {
            v = *(const float4*)(g_upd + ((size_t)bh*U + (r-1))*D + d4*4);
        } else {
            v = ((float4*)tile)[q*16 + d4];
            const float* ofp = &offs[q >> 5][d4*4];
            v.x += ofp[0]; v.y += ofp[1]; v.z += ofp[2]; v.w += ofp[3];
        }
        *(float4*)(out + base + (size_t)q*HD + d4*4) = v;
    }
}

// ---------------------------------------------------------------------------
extern "C" void kernel_launch(void* const* d_in, const int* in_sizes, int n_in,
                              void* d_out, int out_size) {
    const float* Q   = (const float*)d_in[0];
    const float* K   = (const float*)d_in[1];
    const float* V   = (const float*)d_in[2];
    const int*   idx = (const int*)d_in[3];
    float* out = (float*)d_out;

    // 1: M scores — one warp per (b,h,q); also clears g_sel and g_flag
    compute_M_kernel<<<B*H*L*32/256, 256>>>(Q, K, idx);
    // 2: top-40 + sparse attention into scratch (per bh)
    topk_attn_kernel<<<B*H, 256>>>(Q, K, V);
    // 3: fused cumsum + select-write of attention rows
    scan_kernel<<<B*H*NCHUNK, 256>>>(V, out);
}

// round 13
// speedup vs baseline: 3.2936x; 1.0506x over previous
#include <cuda_runtime.h>
#include <math.h>

#define B 4
#define L 2048
#define H 8
#define D 64
#define S 40
#define U 40
#define HD (H*D)
#define CHUNK 128
#define NCHUNK (L/CHUNK)     /* 16 scan chunks */
#define SCALE 0.125f         /* 1/sqrt(64) */

// scratch (allocation-free rule: __device__ globals)
__device__ float g_M[B*H*L];
__device__ int   g_top[B*H*U];
__device__ float g_agg[B*H*NCHUNK*D];    // scan chunk aggregates
__device__ int   g_flag[B*H*NCHUNK];     // lookback flags

// ---------------------------------------------------------------------------
// Kernel 1: M[b,h,q] = max_s dot(Q[b,h,q], K[b,h,idx[q,s]]) - sum_s/L
// One warp per (b,h,q). 4 groups of 8 lanes; each group owns one key per
// batch and reads its 256B row as 2x(8 lanes x 16B) = ONE 128B line per LDG.
// Also clears g_flag (runs first in stream).
// ---------------------------------------------------------------------------
__global__ void compute_M_kernel(const float* __restrict__ Q,
                                 const float* __restrict__ K,
                                 const int*   __restrict__ idx) {
    if (threadIdx.x == 0 && blockIdx.x < B*H*NCHUNK) g_flag[blockIdx.x] = 0;

    int gw   = (blockIdx.x * blockDim.x + threadIdx.x) >> 5;
    int lane = threadIdx.x & 31;
    if (gw >= B*H*L) return;
    int q = gw % L;
    int h = (gw / L) % H;
    int b = gw / (L*H);
    int g   = lane >> 3;     // group 0..3: which key in the batch
    int sub = lane & 7;      // 16B slice within the 128B half-row

    const float4* qrow = (const float4*)(Q + ((size_t)b*L + q)*HD + (size_t)h*D);
    float4 q0 = qrow[sub];        // dims [4*sub   .. 4*sub+3]
    float4 q1 = qrow[8 + sub];    // dims [32+4*sub .. ]

    int k0v = __ldg(idx + q*S + lane);
    int k1v = (lane < 8) ? __ldg(idx + q*S + 32 + lane) : 0;

    const size_t bhK = ((size_t)b*L)*HD + (size_t)h*D;

    float mx = -INFINITY, sm = 0.f;
    #pragma unroll
    for (int t = 0; t < 10; t++) {
        int srcl = t*4 + g;
        int kk = (srcl < 32) ? __shfl_sync(0xffffffffu, k0v, srcl)
                             : __shfl_sync(0xffffffffu, k1v, srcl - 32);
        const float4* krow = (const float4*)(K + bhK + (size_t)kk*HD);
        float4 k0 = krow[sub];
        float4 k1 = krow[8 + sub];
        float p = q0.x*k0.x + q0.y*k0.y + q0.z*k0.z + q0.w*k0.w
                + q1.x*k1.x + q1.y*k1.y + q1.z*k1.z + q1.w*k1.w;
        // reduce within the 8-lane group -> full 64-dim dot on every lane
        p += __shfl_xor_sync(0xffffffffu, p, 1);
        p += __shfl_xor_sync(0xffffffffu, p, 2);
        p += __shfl_xor_sync(0xffffffffu, p, 4);
        mx = fmaxf(mx, p);
        sm += p;
    }
    // reduce across the 4 groups
    mx = fmaxf(mx, __shfl_xor_sync(0xffffffffu, mx, 8));
    sm += __shfl_xor_sync(0xffffffffu, sm, 8);
    mx = fmaxf(mx, __shfl_xor_sync(0xffffffffu, mx, 16));
    sm += __shfl_xor_sync(0xffffffffu, sm, 16);

    if (lane == 0) g_M[gw] = mx - sm * (1.0f/(float)L);
}

// ---------------------------------------------------------------------------
// Kernel 2: top-40 per (b,h), descending, ties -> smaller index (lax.top_k).
// One warp per (b,h); register-resident order-preserving uint32 values,
// packed (val, ~idx) u64 butterfly max; loser lane rescans its 64 slots.
// ---------------------------------------------------------------------------
__device__ __forceinline__ unsigned order_f32(float v) {
    unsigned u = __float_as_uint(v);
    return (u & 0x80000000u) ? ~u : (u | 0x80000000u);
}

__global__ void topk_kernel() {
    int bh   = blockIdx.x;
    int lane = threadIdx.x;           // block = 32
    const float* M = g_M + bh*L;

    unsigned ov[64];
    #pragma unroll
    for (int j = 0; j < 64; j++) ov[j] = order_f32(M[j*32 + lane]);

    unsigned long long removed = 0ull;
    unsigned bv = 0; int bslot = 0;
    #pragma unroll
    for (int j = 0; j < 64; j++) if (ov[j] > bv) { bv = ov[j]; bslot = j; }

    for (int u = 0; u < U; u++) {
        unsigned long long key =
            ((unsigned long long)bv << 32) | (unsigned)(~(unsigned)(bslot*32 + lane));
        #pragma unroll
        for (int o = 16; o > 0; o >>= 1) {
            unsigned long long ok = __shfl_xor_sync(0xffffffffu, key, o);
            if (ok > key) key = ok;
        }
        int widx = (int)(~(unsigned)key);
        if (lane == 0) g_top[bh*U + u] = widx;
        if ((widx & 31) == lane) {
            removed |= 1ull << (widx >> 5);
            bv = 0; bslot = 0;
            #pragma unroll
            for (int j = 0; j < 64; j++) {
                unsigned v = ((removed >> j) & 1ull) ? 0u : ov[j];
                if (v > bv) { bv = v; bslot = j; }
            }
        }
    }
}

// ---------------------------------------------------------------------------
// Kernel 3: fused cumsum(V) over L via decoupled lookback. One kernel, one V
// read, one out write. Block = (bh, c); all 512 blocks resident in one wave.
// (Exact form that passed at R7 and R8.)
// ---------------------------------------------------------------------------
__global__ void scan_kernel(const float* __restrict__ V, float* __restrict__ out) {
    int blk = blockIdx.x;
    int c   = blk & (NCHUNK-1);
    int bh  = blk >> 4;
    int h   = bh & (H-1), b = bh >> 3;
    int t   = threadIdx.x;            // 256
    __shared__ float tile[CHUNK*D];   // 32KB
    __shared__ float part[4][64];
    __shared__ float offs[4][64];

    size_t base = (((size_t)b*L + (size_t)c*CHUNK))*HD + (size_t)h*D;
    for (int e = t; e < CHUNK*D/4; e += 256) {
        int q = e >> 4, d4 = e & 15;
        ((float4*)tile)[q*16 + d4] = *(const float4*)(V + base + (size_t)q*HD + d4*4);
    }
    __syncthreads();

    // intra-part serial scan: 4 parts x 64 d-lanes, 32 rows each
    int p = t >> 6, d = t & 63;
    {
        float acc = 0.f;
        #pragma unroll
        for (int i = 0; i < 32; i++) {
            acc += tile[(p*32 + i)*64 + d];
            tile[(p*32 + i)*64 + d] = acc;
        }
        part[p][d] = acc;
    }
    __syncthreads();

    // publish chunk aggregate (release)
    if (t < 64) g_agg[blk*D + t] = part[0][t] + part[1][t] + part[2][t] + part[3][t];
    __syncthreads();
    if (t == 0) { __threadfence(); atomicExch(&g_flag[blk], 1); }

    // lookback: wait for all predecessors, then sum their aggregates
    if (t < c) while (atomicAdd(&g_flag[bh*NCHUNK + t], 0) == 0) {}
    __syncthreads();
    __threadfence();
    if (t < 64) {
        float o = 0.f;
        for (int cc = 0; cc < c; cc++) o += g_agg[(bh*NCHUNK + cc)*D + t];
        offs[0][t] = o;          o += part[0][t];
        offs[1][t] = o;          o += part[1][t];
        offs[2][t] = o;          o += part[2][t];
        offs[3][t] = o;
    }
    __syncthreads();

    for (int e = t; e < CHUNK*D/4; e += 256) {
        int q = e >> 4, d4 = e & 15;
        float4 v  = ((float4*)tile)[q*16 + d4];
        const float* ofp = &offs[q >> 5][d4*4];
        v.x += ofp[0]; v.y += ofp[1]; v.z += ofp[2]; v.w += ofp[3];
        *(float4*)(out + base + (size_t)q*HD + d4*4) = v;
    }
}

// ---------------------------------------------------------------------------
// Kernel 4: attention for the 40 selected queries per (b,h); scatter into out.
// Rank-i row attends only keys 0..i (Informer mask quirk: mask is triu(u,L)).
// Grid = (bh, group of 4 rows) = 320 blocks of 128; one warp per output row.
// Loads only the K/V rows its group can reference (0..4g+3).
// ---------------------------------------------------------------------------
__global__ void attn_kernel(const float* __restrict__ Q,
                            const float* __restrict__ K,
                            const float* __restrict__ V,
                            float* __restrict__ out) {
    int g  = blockIdx.x % 10;
    int bh = blockIdx.x / 10;
    int h  = bh & (H-1), b = bh >> 3;
    int t  = threadIdx.x;     // 128 = 4 warps
    __shared__ float Ks[U][D+1], Vs[U][D+1], Qs[4][D+1];
    __shared__ int ti[4];

    if (t < 4) ti[t] = g_top[bh*U + g*4 + t];
    __syncthreads();

    int kmax = g*4 + 4;                           // rows 0..kmax-1 needed
    for (int e = t; e < kmax*D; e += 128) {
        int r = e >> 6, d = e & 63;
        Ks[r][d] = K[((size_t)b*L + r)*HD + (size_t)h*D + d];
        Vs[r][d] = V[((size_t)b*L + r)*HD + (size_t)h*D + d];
    }
    for (int e = t; e < 4*D; e += 128) {
        int r = e >> 6, d = e & 63;
        Qs[r][d] = Q[((size_t)b*L + ti[r])*HD + (size_t)h*D + d];
    }
    __syncthreads();

    int warp = t >> 5, lane = t & 31;
    int i   = g*4 + warp;                         // output row rank 0..39
    int k1  = (lane < kmax) ? lane : 0;           // clamp to loaded rows
    int k2l = lane + 32;
    int k2  = (k2l < kmax) ? k2l : 0;

    bool v0 = (lane <= i);
    bool v1 = (k2l < U) && (k2l <= i);

    float s0 = 0.f, s1 = 0.f;
    #pragma unroll
    for (int d = 0; d < D; d++) {
        float qd = Qs[warp][d];
        s0 += qd * Ks[k1][d];
        s1 += qd * Ks[k2][d];
    }
    s0 *= SCALE; s1 *= SCALE;

    float mx = fmaxf(v0 ? s0 : -INFINITY, v1 ? s1 : -INFINITY);
    #pragma unroll
    for (int o = 16; o > 0; o >>= 1)
        mx = fmaxf(mx, __shfl_xor_sync(0xffffffffu, mx, o));

    float e0 = v0 ? __expf(s0 - mx) : 0.f;
    float e1 = v1 ? __expf(s1 - mx) : 0.f;
    float den = e0 + e1;
    #pragma unroll
    for (int o = 16; o > 0; o >>= 1)
        den += __shfl_xor_sync(0xffffffffu, den, o);
    float inv = __frcp_rn(den);
    float w0 = e0 * inv, w1 = e1 * inv;

    float a0 = 0.f, a1 = 0.f;
    int klim = (i < 31) ? i : 31;
    for (int k = 0; k <= klim; k++) {
        float w = __shfl_sync(0xffffffffu, w0, k);
        a0 += w * Vs[k][lane];
        a1 += w * Vs[k][lane+32];
    }
    for (int k = 32; k <= i; k++) {               // only when i >= 32
        float w = __shfl_sync(0xffffffffu, w1, k - 32);
        a0 += w * Vs[k][lane];
        a1 += w * Vs[k][lane+32];
    }

    float* op = out + ((size_t)b*L + ti[warp])*HD + (size_t)h*D;
    op[lane]      = a0;
    op[lane + 32] = a1;
}

// ---------------------------------------------------------------------------
extern "C" void kernel_launch(void* const* d_in, const int* in_sizes, int n_in,
                              void* d_out, int out_size) {
    const float* Q   = (const float*)d_in[0];
    const float* K   = (const float*)d_in[1];
    const float* V   = (const float*)d_in[2];
    const int*   idx = (const int*)d_in[3];
    float* out = (float*)d_out;

    // 1: M scores — one warp per (b,h,q); also clears g_flag
    compute_M_kernel<<<B*H*L*32/256, 256>>>(Q, K, idx);
    // 2: top-40 per (b,h) — one warp per (b,h)
    topk_kernel<<<B*H, 32>>>();
    // 3: fused single-pass cumsum of V (decoupled lookback)
    scan_kernel<<<B*H*NCHUNK, 256>>>(V, out);
    // 4: sparse attention + scatter (after cumsum writes)
    attn_kernel<<<B*H*10, 128>>>(Q, K, V, out);
}